// round 12
// baseline (speedup 1.0000x reference)
#include <cuda_runtime.h>
#include <cstdint>

typedef unsigned long long ull;

#define SEQ    512
#define BATCH  128
#define INPUT  128
#define HIDDEN 512
#define CLUSTER 8
#define THREADS 512
#define NCHAIN  4

// ---- recurrent smem layout (bytes) ----
// W slice  [512 k][64 n] fp32                          131072
// hc: [c 4][par 2][k 512][b 2] fp32 (4096 each)         32768
// stg: [c 4][par 2][n 64][b 2] fp32 (512 each)           4096
// scr: [c 4][kq 16][b 2][n 64] fp32 (8192 each)         32768
// mbar: [c 4][par 2][src 8] x 8B                           512
#define HC_OFF   131072
#define STG_OFF  163840
#define SCR_OFF  167936
#define MB_OFF   200704
#define SMEM_BYTES 201216
#define EXCH_BYTES 512u      // per (chain,parity,src) barrier: one 512B chunk

// ---------------------------------------------------------------------------
// Phase 1: proj[row,n] = sum_k input[row,k] * W_in[n,k] -> d_out
// ---------------------------------------------------------------------------
__global__ __launch_bounds__(256) void proj_kernel(
    const float* __restrict__ A, const float* __restrict__ W,
    float* __restrict__ C)
{
    __shared__ float As[64][65];
    __shared__ float Bs[64][65];
    const int tid = threadIdx.x, tx = tid & 15, ty = tid >> 4;
    const int row0 = blockIdx.x * 64, n0 = blockIdx.y * 64;
    float acc[4][4] = {};
    for (int k0 = 0; k0 < INPUT; k0 += 64) {
        #pragma unroll
        for (int i = 0; i < 16; i++) {
            int e = tid + i * 256, r = e >> 6, kk = e & 63;
            As[kk][r] = A[(row0 + r) * INPUT + k0 + kk];
            Bs[kk][r] = W[(n0 + r) * INPUT + k0 + kk];
        }
        __syncthreads();
        #pragma unroll 8
        for (int k = 0; k < 64; k++) {
            float a[4], b[4];
            #pragma unroll
            for (int i = 0; i < 4; i++) a[i] = As[k][ty * 4 + i];
            #pragma unroll
            for (int j = 0; j < 4; j++) b[j] = Bs[k][tx * 4 + j];
            #pragma unroll
            for (int i = 0; i < 4; i++)
                #pragma unroll
                for (int j = 0; j < 4; j++) acc[i][j] += a[i] * b[j];
        }
        __syncthreads();
    }
    #pragma unroll
    for (int i = 0; i < 4; i++) {
        int row = row0 + ty * 4 + i;
        #pragma unroll
        for (int j = 0; j < 4; j++)
            C[row * HIDDEN + n0 + tx * 4 + j] = acc[i][j];
    }
}

// ---- helpers ---------------------------------------------------------------
__device__ __forceinline__ void fma2(ull& d, ull a, ull b) {
    asm("fma.rn.f32x2 %0, %1, %2, %0;" : "+l"(d) : "l"(a), "l"(b));
}
__device__ __forceinline__ ull pk(float lo, float hi) {
    ull d; asm("mov.b64 %0, {%1, %2};" : "=l"(d) : "f"(lo), "f"(hi)); return d;
}
__device__ __forceinline__ uint32_t s2u(const void* p) {
    uint32_t a;
    asm("{ .reg .u64 t; cvta.to.shared.u64 t, %1; cvt.u32.u64 %0, t; }" : "=r"(a) : "l"(p));
    return a;
}

#define MB_WAIT(mb, ph) do {                                                    \
    uint32_t _done;                                                             \
    asm volatile("{\n\t.reg .pred p;\n\t"                                       \
        "mbarrier.try_wait.parity.acquire.cluster.shared::cta.b64 p, [%1], %2;\n\t" \
        "selp.b32 %0, 1, 0, p;\n\t}"                                            \
        : "=r"(_done) : "r"(mb), "r"(ph) : "memory");                           \
    while (!_done) {                                                            \
        asm volatile("{\n\t.reg .pred p;\n\t"                                   \
            "mbarrier.try_wait.parity.acquire.cluster.shared::cta.b64 p, [%1], %2, 0x989680;\n\t" \
            "selp.b32 %0, 1, 0, p;\n\t}"                                        \
            : "=r"(_done) : "r"(mb), "r"(ph) : "memory");                       \
    }                                                                           \
} while (0)

#define MB_ARM(mb)                                                              \
    asm volatile("mbarrier.arrive.expect_tx.shared.b64 _, [%0], %1;"            \
                 :: "r"(mb), "r"(EXCH_BYTES) : "memory")

#define BULK_CLUSTER(dst, src, bytes, mb)                                       \
    asm volatile("cp.async.bulk.shared::cluster.shared::cta.mbarrier::complete_tx::bytes " \
                 "[%0], [%1], %2, [%3];"                                        \
                 :: "r"(dst), "r"(src), "r"(bytes), "r"(mb) : "memory")

// ---------------------------------------------------------------------------
// Phase 2: persistent cluster recurrence, FOUR chains TIME-MULTIPLEXED on all
//   512 threads (anti-phase by construction). 16 clusters x 8 CTAs; rank owns
//   64 hidden cols; cluster owns 8 batch rows; chain c owns rows {2c, 2c+1}.
//   Per chain-step: per-warp chunk wait -> full-SM matvec -> bar -> reduce/
//   update by warps 0-3 -> bar -> 8 x 512B bulk sends. Chain c's fabric
//   flight hides behind chains c+1..c+3's compute.
// ---------------------------------------------------------------------------
__global__ void __launch_bounds__(THREADS, 1) __cluster_dims__(CLUSTER, 1, 1)
recurrent_kernel(const float* __restrict__ Whid,
                 const float* __restrict__ noise,
                 float* __restrict__ out, int has_tail)
{
    extern __shared__ float sm[];
    const uint32_t sbase = s2u(sm);

    const int tid = threadIdx.x;
    uint32_t rank;
    asm("mov.u32 %0, %%cluster_ctarank;" : "=r"(rank));
    const int n0r   = (int)rank * 64;
    const int bbase = (blockIdx.x >> 3) * 8;

    // ---- load W slice transposed: Ws[k*64+n] = Whid[n0r+n][k] ----
    for (int i = tid; i < 64 * 128; i += THREADS) {
        int n = i >> 7, kq4 = i & 127;
        float4 v = reinterpret_cast<const float4*>(Whid)[(n0r + n) * 128 + kq4];
        sm[(4 * kq4 + 0) * 64 + n] = v.x;
        sm[(4 * kq4 + 1) * 64 + n] = v.y;
        sm[(4 * kq4 + 2) * 64 + n] = v.z;
        sm[(4 * kq4 + 3) * 64 + n] = v.w;
    }
    // ---- zero parity-0 hc buffers, all 4 chains (h0 = 0 -> relu = 0) ----
    for (int i = tid; i < 4096; i += THREADS) {
        int c = i >> 10, j = i & 1023;
        sm[HC_OFF / 4 + c * 2048 + j] = 0.0f;
    }
    // ---- init + pre-arm all 64 chunk mbarriers ----
    if (tid == 0) {
        for (int m = 0; m < 64; m++) {
            uint32_t mb = sbase + MB_OFF + m * 8;
            asm volatile("mbarrier.init.shared.b64 [%0], %1;" :: "r"(mb), "r"(1u) : "memory");
        }
        asm volatile("fence.proxy.async.shared::cta;" ::: "memory");
        for (int m = 0; m < 64; m++) MB_ARM(sbase + MB_OFF + m * 8);
    }
    __syncthreads();
    asm volatile("barrier.cluster.arrive.aligned;" ::: "memory");
    asm volatile("barrier.cluster.wait.aligned;"   ::: "memory");

    // ---- thread mapping ----
    // matvec: warp kq (16 x 32k), lane ng (32 n-pairs); src rank = kq>>1
    const int kq   = tid >> 5;
    const int ng   = tid & 31;
    const int srcw = kq >> 1;
    const uint32_t wp0 = sbase + (uint32_t)(kq * 8192 + ng * 8);
    // reduce/epilogue (tid < 128): output (rb, col); chain c -> row bbase+2c+rb
    const int rb  = tid >> 6;            // 0..1 (valid for tid<128)
    const int rn  = tid & 63;
    const int col = n0r + rn;
    // peer CTA smem bases
    uint32_t peer[CLUSTER];
    #pragma unroll
    for (int r = 0; r < CLUSTER; r++)
        asm("mapa.shared::cluster.u32 %0, %1, %2;" : "=r"(peer[r]) : "r"(sbase), "r"(r));

    float rh[NCHAIN] = {0.f, 0.f, 0.f, 0.f};
    float xc[NCHAIN] = {0.f, 0.f, 0.f, 0.f};
    int ph0[NCHAIN]  = {0, 0, 0, 0};
    int ph1[NCHAIN]  = {0, 0, 0, 0};
    float nz = 0.0f;

    // prologue prefetch for s=0 (proj already in d_out)
    if (tid < 128) {
        nz = __ldg(&noise[col]);
        #pragma unroll
        for (int c = 0; c < NCHAIN; c++)
            xc[c] = out[((size_t)(bbase + c * 2 + rb)) * HIDDEN + col];
    }

    for (int s = 0; s < SEQ; s++) {
        const int par = s & 1;
        const int pn  = par ^ 1;
        float nzn = nz;

        #pragma unroll
        for (int c = 0; c < NCHAIN; c++) {
            // ---- per-warp chunk wait (src = srcw) ----
            if (s > 0) {
                uint32_t mb = sbase + (uint32_t)(MB_OFF + ((c * 2 + par) * 8 + srcw) * 8);
                if (par) MB_WAIT(mb, ph1[c]); else MB_WAIT(mb, ph0[c]);
                if ((tid & 63) == 0) MB_ARM(mb);     // one re-armer per src barrier
                if (par) ph1[c] ^= 1; else ph0[c] ^= 1;
            }
            // ---- prefetch next step's proj/noise (hidden behind matvec) ----
            float xn = 0.0f;
            if (tid < 128 && s + 1 < SEQ) {
                xn = out[((size_t)(s + 1) * BATCH + bbase + c * 2 + rb) * HIDDEN + col];
                if (c == 0) nzn = __ldg(&noise[(size_t)(s + 1) * HIDDEN + col]);
            }
            // ---- full-SM matvec for chain c: thread = 2b x 2n x 32k ----
            const uint32_t hp0 = sbase + (uint32_t)(HC_OFF + c * 8192 + par * 4096 + kq * 256);
            ull a0 = 0, a1 = 0;
            #pragma unroll 8
            for (int k = 0; k < 32; k++) {
                ull w; float h0, h1;
                asm("ld.shared.u64 %0, [%1];" : "=l"(w) : "r"(wp0 + (uint32_t)(k * 256)));
                asm("ld.shared.v2.f32 {%0,%1}, [%2];"
                    : "=f"(h0), "=f"(h1) : "r"(hp0 + (uint32_t)(k * 8)));
                fma2(a0, pk(h0, h0), w);
                fma2(a1, pk(h1, h1), w);
            }
            {
                uint32_t sst = sbase + (uint32_t)(SCR_OFF + c * 8192 + kq * 512 + ng * 8);
                asm volatile("st.shared.u64 [%0],     %1;" :: "r"(sst), "l"(a0));
                asm volatile("st.shared.u64 [%0+256], %1;" :: "r"(sst), "l"(a1));
            }
            __syncthreads();   // partials visible

            // ---- reduce 16 k-partials + state update (warps 0-3) ----
            if (tid < 128) {
                uint32_t srd = sbase + (uint32_t)(SCR_OFF + c * 8192 + rb * 256 + rn * 4);
                float acc = 0.0f;
                #pragma unroll
                for (int q = 0; q < 16; q++) {
                    float v;
                    asm("ld.shared.f32 %0, [%1];" : "=f"(v) : "r"(srd + (uint32_t)(q * 512)));
                    acc += v;
                }
                float hn = 0.5f * rh[c] + 0.5f * (acc + xc[c] + nz);
                rh[c] = hn;
                out[((size_t)s * BATCH + bbase + c * 2 + rb) * HIDDEN + col] = hn;
                xc[c] = xn;
                if (s + 1 < SEQ) {
                    uint32_t stg = sbase + (uint32_t)(STG_OFF + c * 1024 + pn * 512
                                                      + (rn * 2 + rb) * 4);
                    asm volatile("st.shared.f32 [%0], %1;"
                                 :: "r"(stg), "f"(fmaxf(hn, 0.0f)) : "memory");
                }
            }
            __syncthreads();   // staging visible; protects scr WAR

            // ---- 8 threads send the 8 bulk copies (512B each) ----
            if (s + 1 < SEQ && tid < 8) {
                asm volatile("fence.proxy.async.shared::cta;" ::: "memory");
                uint32_t src    = sbase + (uint32_t)(STG_OFF + c * 1024 + pn * 512);
                uint32_t dstoff = (uint32_t)(HC_OFF + c * 8192 + pn * 4096 + (int)rank * 512);
                uint32_t mboff  = (uint32_t)(MB_OFF + ((c * 2 + pn) * 8 + (int)rank) * 8);
                BULK_CLUSTER(peer[tid] + dstoff, src, 512u, peer[tid] + mboff);
            }
        }
        nz = nzn;
    }

    // ---- fused tail: final hidden state ----
    if (has_tail && tid < 128) {
        #pragma unroll
        for (int c = 0; c < NCHAIN; c++)
            out[(size_t)SEQ * BATCH * HIDDEN
                + (size_t)(bbase + c * 2 + rb) * HIDDEN + col] = rh[c];
    }

    // keep smem alive until all cluster peers are done
    asm volatile("barrier.cluster.arrive.aligned;" ::: "memory");
    asm volatile("barrier.cluster.wait.aligned;"   ::: "memory");
}

// ---------------------------------------------------------------------------
extern "C" void kernel_launch(void* const* d_in, const int* in_sizes, int n_in,
                              void* d_out, int out_size)
{
    const float* input = (const float*)d_in[0];
    const float* W_in  = (const float*)d_in[1];
    const float* W_hid = (const float*)d_in[2];
    const float* noise = (const float*)d_in[3];
    float* out = (float*)d_out;

    cudaFuncSetAttribute(recurrent_kernel,
                         cudaFuncAttributeMaxDynamicSharedMemorySize, SMEM_BYTES);

    dim3 grid((SEQ * BATCH) / 64, HIDDEN / 64);
    proj_kernel<<<grid, 256>>>(input, W_in, out);

    int has_tail = (out_size >= SEQ * BATCH * HIDDEN + BATCH * HIDDEN) ? 1 : 0;
    recurrent_kernel<<<128, THREADS, SMEM_BYTES>>>(W_hid, noise, out, has_tail);
}

// round 13
// speedup vs baseline: 1.8763x; 1.8763x over previous
#include <cuda_runtime.h>
#include <cstdint>

typedef unsigned long long ull;

#define SEQ    512
#define BATCH  128
#define INPUT  128
#define HIDDEN 512
#define THREADS 512

// ---- recurrent smem layout (bytes) ----
// W slice  [512 k][64 n] fp32                          131072
// HS chunk staging: [e 2][k 512][b 4] fp32              16384
// scr partials: [e 2][kq 8][b 4][n 64] fp32             16384
#define HS_OFF   131072
#define SCR_OFF  147456
#define SMEM_BYTES 163840

// ---- global exchange state (no allocations allowed) ----
__device__ float    g_h[2][BATCH * HIDDEN];        // relu(h), parity buffered
__device__ unsigned g_flags[16][2][8 * 32];        // [group][engine][src*32] 128B-spaced

// ---------------------------------------------------------------------------
// init: zero g_h[0] (h0 = 0) and all flags (every launch -> deterministic)
// ---------------------------------------------------------------------------
__global__ void init_kernel()
{
    int i = blockIdx.x * blockDim.x + threadIdx.x;
    if (i < BATCH * HIDDEN) g_h[0][i] = 0.0f;
    if (i < 16 * 2 * 8 * 32) ((unsigned*)g_flags)[i] = 0u;
}

// ---------------------------------------------------------------------------
// Phase 1: proj[row,n] = sum_k input[row,k] * W_in[n,k] -> d_out
// ---------------------------------------------------------------------------
__global__ __launch_bounds__(256) void proj_kernel(
    const float* __restrict__ A, const float* __restrict__ W,
    float* __restrict__ C)
{
    __shared__ float As[64][65];
    __shared__ float Bs[64][65];
    const int tid = threadIdx.x, tx = tid & 15, ty = tid >> 4;
    const int row0 = blockIdx.x * 64, n0 = blockIdx.y * 64;
    float acc[4][4] = {};
    for (int k0 = 0; k0 < INPUT; k0 += 64) {
        #pragma unroll
        for (int i = 0; i < 16; i++) {
            int e = tid + i * 256, r = e >> 6, kk = e & 63;
            As[kk][r] = A[(row0 + r) * INPUT + k0 + kk];
            Bs[kk][r] = W[(n0 + r) * INPUT + k0 + kk];
        }
        __syncthreads();
        #pragma unroll 8
        for (int k = 0; k < 64; k++) {
            float a[4], b[4];
            #pragma unroll
            for (int i = 0; i < 4; i++) a[i] = As[k][ty * 4 + i];
            #pragma unroll
            for (int j = 0; j < 4; j++) b[j] = Bs[k][tx * 4 + j];
            #pragma unroll
            for (int i = 0; i < 4; i++)
                #pragma unroll
                for (int j = 0; j < 4; j++) acc[i][j] += a[i] * b[j];
        }
        __syncthreads();
    }
    #pragma unroll
    for (int i = 0; i < 4; i++) {
        int row = row0 + ty * 4 + i;
        #pragma unroll
        for (int j = 0; j < 4; j++)
            C[row * HIDDEN + n0 + tx * 4 + j] = acc[i][j];
    }
}

// ---- helpers ---------------------------------------------------------------
__device__ __forceinline__ void fma2(ull& d, ull a, ull b) {
    asm("fma.rn.f32x2 %0, %1, %2, %0;" : "+l"(d) : "l"(a), "l"(b));
}
__device__ __forceinline__ ull pk(float lo, float hi) {
    ull d; asm("mov.b64 %0, {%1, %2};" : "=l"(d) : "f"(lo), "f"(hi)); return d;
}
__device__ __forceinline__ uint32_t s2u(const void* p) {
    uint32_t a;
    asm("{ .reg .u64 t; cvta.to.shared.u64 t, %1; cvt.u32.u64 %0, t; }" : "=r"(a) : "l"(p));
    return a;
}

// ---------------------------------------------------------------------------
// Phase 2: persistent recurrence, NO clusters. 128 CTAs (all resident):
//   group g = blockIdx/8 owns batch rows [8g,8g+8); rank = blockIdx%8 owns
//   hidden cols [64r,64r+64). Two engines (4 rows each) as R11.
//   Exchange via L2: producers store relu(h) to g_h[par^1] + monotonic flag;
//   consumer warp kq polls flag[g][e][kq] >= s (acquire), stages its 1KB
//   chunk L2->smem, then runs the R11 matvec. No mbarriers, no bulk engine.
// ---------------------------------------------------------------------------
__global__ void __launch_bounds__(THREADS, 1)
recurrent_kernel(const float* __restrict__ Whid,
                 const float* __restrict__ noise,
                 float* __restrict__ out, int has_tail)
{
    extern __shared__ float sm[];
    const uint32_t sbase = s2u(sm);

    const int tid   = threadIdx.x;
    const int g     = blockIdx.x >> 3;
    const int rank  = blockIdx.x & 7;
    const int n0r   = rank * 64;
    const int bbase = g * 8;

    // ---- load W slice transposed: Ws[k*64+n] = Whid[n0r+n][k] ----
    for (int i = tid; i < 64 * 128; i += THREADS) {
        int n = i >> 7, kq4 = i & 127;
        float4 v = reinterpret_cast<const float4*>(Whid)[(n0r + n) * 128 + kq4];
        sm[(4 * kq4 + 0) * 64 + n] = v.x;
        sm[(4 * kq4 + 1) * 64 + n] = v.y;
        sm[(4 * kq4 + 2) * 64 + n] = v.z;
        sm[(4 * kq4 + 3) * 64 + n] = v.w;
    }
    __syncthreads();

    // ---- engine / thread mapping (R11) ----
    const int e    = tid >> 8;           // engine 0/1
    const int etid = tid & 255;
    // matvec: kq (8 x 64k == source rank) x bg (2 x 2b) x ng (16 x 4n)
    const int kq = etid >> 5;
    const int ng = etid & 15;
    const int bg = (etid >> 4) & 1;
    const uint32_t wp0 = sbase + (uint32_t)(kq * 16384 + ng * 16);
    // reduce/epilogue: one output (b, col) per thread
    const int rb   = etid >> 6;          // 0..3
    const int rn   = etid & 63;
    const int col  = n0r + rn;
    const int gb   = bbase + e * 4 + rb;
    const uint32_t scr_st = sbase + SCR_OFF + (uint32_t)((e * 2048 + kq * 256 + 2 * bg * 64 + 4 * ng) * 4);
    const uint32_t scr_rd = sbase + SCR_OFF + (uint32_t)((e * 2048 + rb * 64 + rn) * 4);
    // staging: lane -> (b_l, kk_l) of this warp's chunk
    const int lane = tid & 31;
    const int b_l  = lane >> 3;          // 0..3
    const int kk_l = (lane & 7) * 8;     // 0..56
    const uint32_t hs_st = sbase + (uint32_t)(HS_OFF + e * 8192 + (kq * 64 + kk_l) * 16 + b_l * 4);
    const uint32_t hp0   = sbase + (uint32_t)(HS_OFF + e * 8192 + kq * 1024 + bg * 8);
    // flags
    unsigned* flagw = &g_flags[g][e][kq * 32];     // this warp waits on src = kq
    unsigned* flagp = &g_flags[g][e][rank * 32];   // this CTA publishes

    float rh = 0.0f;

    for (int s = 0; s < SEQ; s++) {
        const int par = s & 1;

        // ---- per-warp chunk wait (monotonic flag) ----
        if (s > 0) {
            unsigned f;
            do {
                asm volatile("ld.acquire.gpu.global.u32 %0, [%1];"
                             : "=r"(f) : "l"(flagw) : "memory");
            } while (f < (unsigned)s);
        }

        // ---- stage this warp's 1KB chunk: g_h[par] -> smem [k][b] ----
        {
            const float* hsrc = &g_h[par][(size_t)(bbase + e * 4 + b_l) * HIDDEN
                                          + kq * 64 + kk_l];
            float4 v0 = *reinterpret_cast<const float4*>(hsrc);
            float4 v1 = *reinterpret_cast<const float4*>(hsrc + 4);
            asm volatile("st.shared.f32 [%0],     %1;" :: "r"(hs_st), "f"(v0.x));
            asm volatile("st.shared.f32 [%0+16],  %1;" :: "r"(hs_st), "f"(v0.y));
            asm volatile("st.shared.f32 [%0+32],  %1;" :: "r"(hs_st), "f"(v0.z));
            asm volatile("st.shared.f32 [%0+48],  %1;" :: "r"(hs_st), "f"(v0.w));
            asm volatile("st.shared.f32 [%0+64],  %1;" :: "r"(hs_st), "f"(v1.x));
            asm volatile("st.shared.f32 [%0+80],  %1;" :: "r"(hs_st), "f"(v1.y));
            asm volatile("st.shared.f32 [%0+96],  %1;" :: "r"(hs_st), "f"(v1.z));
            asm volatile("st.shared.f32 [%0+112], %1;" :: "r"(hs_st), "f"(v1.w));
        }
        __syncwarp();

        // prefetch proj (in d_out) + noise for the epilogue
        float* optr = out + ((size_t)s * BATCH + gb) * HIDDEN + col;
        float x  = *optr;
        float nz = __ldg(&noise[(size_t)s * HIDDEN + col]);

        // ---- matvec over this warp's 64-k chunk (R11 tile) ----
        ull a00 = 0, a01 = 0, a10 = 0, a11 = 0;
        #pragma unroll 8
        for (int k = 0; k < 64; k++) {
            ull w01, w23;
            float hx, hy;
            asm("ld.shared.v2.u64 {%0,%1}, [%2];"
                : "=l"(w01), "=l"(w23) : "r"(wp0 + (uint32_t)(k * 256)));
            asm("ld.shared.v2.f32 {%0,%1}, [%2];"
                : "=f"(hx), "=f"(hy) : "r"(hp0 + (uint32_t)(k * 16)));
            ull h0 = pk(hx, hx), h1 = pk(hy, hy);
            fma2(a00, h0, w01); fma2(a01, h0, w23);
            fma2(a10, h1, w01); fma2(a11, h1, w23);
        }
        asm volatile("st.shared.v2.u64 [%0],     {%1,%2};" :: "r"(scr_st), "l"(a00), "l"(a01));
        asm volatile("st.shared.v2.u64 [%0+256], {%1,%2};" :: "r"(scr_st), "l"(a10), "l"(a11));

        // engine barrier #1: matvec partials visible
        asm volatile("bar.sync %0, 256;" :: "r"(1 + e) : "memory");

        // ---- reduce 8 k-partials + state update ----
        float acc = 0.0f;
        #pragma unroll
        for (int q = 0; q < 8; q++) {
            float v;
            asm("ld.shared.f32 %0, [%1];" : "=f"(v) : "r"(scr_rd + (uint32_t)(q * 1024)));
            acc += v;
        }
        float hn = 0.5f * rh + 0.5f * (acc + x + nz);
        rh = hn;
        *optr = hn;

        if (s < SEQ - 1) {
            // publish relu(h_new) to L2 (coalesced rows)
            g_h[par ^ 1][(size_t)gb * HIDDEN + col] = fmaxf(hn, 0.0f);

            // engine barrier #2: all publishes done; also protects scr/HS WAR
            asm volatile("bar.sync %0, 256;" :: "r"(1 + e) : "memory");

            if (etid == 0) {
                __threadfence();   // order data stores before the flag at gpu scope
                unsigned nf = (unsigned)(s + 1);
                asm volatile("st.relaxed.gpu.global.u32 [%0], %1;"
                             :: "l"(flagp), "r"(nf) : "memory");
            }
        }
    }

    // ---- fused tail: final hidden state ----
    if (has_tail)
        out[(size_t)SEQ * BATCH * HIDDEN + (size_t)gb * HIDDEN + col] = rh;
}

// ---------------------------------------------------------------------------
extern "C" void kernel_launch(void* const* d_in, const int* in_sizes, int n_in,
                              void* d_out, int out_size)
{
    const float* input = (const float*)d_in[0];
    const float* W_in  = (const float*)d_in[1];
    const float* W_hid = (const float*)d_in[2];
    const float* noise = (const float*)d_in[3];
    float* out = (float*)d_out;

    cudaFuncSetAttribute(recurrent_kernel,
                         cudaFuncAttributeMaxDynamicSharedMemorySize, SMEM_BYTES);

    init_kernel<<<288, 256>>>();

    dim3 grid((SEQ * BATCH) / 64, HIDDEN / 64);
    proj_kernel<<<grid, 256>>>(input, W_in, out);

    int has_tail = (out_size >= SEQ * BATCH * HIDDEN + BATCH * HIDDEN) ? 1 : 0;
    recurrent_kernel<<<128, THREADS, SMEM_BYTES>>>(W_hid, noise, out, has_tail);
}